// round 10
// baseline (speedup 1.0000x reference)
#include <cuda_runtime.h>
#include <math.h>
#include <stdint.h>

#define Bx 4
#define Sx 128
#define Dx 256
#define Hx 8

static __device__ float g_Vp [2][Bx*Sx*Dx];   // V partials (K halves), no bias
static __device__ float g_QKp[2][Bx*Sx*64];   // QK partials, no bias
static __device__ float g_AO [Bx*Sx*Dx];      // attention output (pre-Wo)
static __device__ float g_Op [2][Bx*Sx*Dx];   // O-GEMM partials, no bias

// ---------------------------------------------------------------------------
// Half-K GEMM: C[m0+m][n0+n] = sum_{k in chunk kc} A[m][k]*B[n][k]  (NT, K=128)
// 32m x 32n, 256 thr. Warp w: n-group ng=w&3 (8 n), k4-parity kp=w>>2.
// Thread: m=lane, 8 n, split accumulators. As/Bs [32][33] f4 padded.
// Partial output, bias added by consumer. qk mode gathers B rows from Wq|Wk:
//   col -> h=col>>3, side=(col>>2)&1, w=col&3, row = h*32+w.
// ---------------------------------------------------------------------------
__device__ __forceinline__ void gemm_half(
    const float4* __restrict__ A4,
    const float4* __restrict__ Bq4, const float4* __restrict__ Bk4,
    float* __restrict__ C, int m0, int n0, int cstride, int qk, int kc,
    float* sm)
{
    float4* As = (float4*)sm;            // [32][33] float4
    float4* Bs = (float4*)sm + 32*33;    // [32][33] float4
    const int tid  = threadIdx.x;
    const int lane = tid & 31;
    const int w    = tid >> 5;
    const int ng   = w & 3;
    const int kp   = w >> 2;

    float acc[8][2];
#pragma unroll
    for (int j = 0; j < 8; j++) { acc[j][0] = 0.f; acc[j][1] = 0.f; }

    const float4* Ap = As + lane*33 + kp;
    const float4* Bp = Bs + (ng*8)*33 + kp;

    // stage the single K-chunk
#pragma unroll
    for (int t = 0; t < 4; t++) {
        const int idx = tid + (t << 8);
        const int r = idx >> 5, c = idx & 31;
        As[r*33 + c] = A4[(m0 + r)*64 + (kc << 5) + c];
        int brow;
        const float4* bp;
        if (qk) {
            const int col = n0 + r;
            brow = ((col >> 3)*32) + (col & 3);
            bp = ((col >> 2) & 1) ? Bk4 : Bq4;
        } else {
            brow = n0 + r;
            bp = Bq4;
        }
        Bs[r*33 + c] = bp[brow*64 + (kc << 5) + c];
    }
    __syncthreads();

#pragma unroll 4
    for (int k4 = 0; k4 < 16; k4++) {
        const float4 a = Ap[k4*2];
#pragma unroll
        for (int j = 0; j < 8; j++) {
            const float4 b = Bp[j*33 + k4*2];
            acc[j][0] = fmaf(a.x, b.x, acc[j][0]);
            acc[j][1] = fmaf(a.y, b.y, acc[j][1]);
            acc[j][0] = fmaf(a.z, b.z, acc[j][0]);
            acc[j][1] = fmaf(a.w, b.w, acc[j][1]);
        }
    }
    __syncthreads();

    // cross-parity reduction through smem (17-pad: conflict-free)
    float* red = sm;
    if (kp == 1) {
#pragma unroll
        for (int j = 0; j < 8; j++) {
            red[(ng*32 + lane)*17 + j*2    ] = acc[j][0];
            red[(ng*32 + lane)*17 + j*2 + 1] = acc[j][1];
        }
    }
    __syncthreads();
    if (kp == 0) {
        const float* rp = &red[(ng*32 + lane)*17];
        float o[8];
#pragma unroll
        for (int j = 0; j < 8; j++)
            o[j] = acc[j][0] + acc[j][1] + rp[j*2] + rp[j*2 + 1];
        float* cp = &C[(m0 + lane)*cstride + n0 + ng*8];
        *(float4*)cp       = make_float4(o[0], o[1], o[2], o[3]);
        *(float4*)(cp + 4) = make_float4(o[4], o[5], o[6], o[7]);
    }
}

// ---------------------------------------------------------------------------
// Kernel 1: V-GEMM (256 blocks: 128 tiles x 2 K-halves)
//         + QK-GEMM (64 blocks: 32 tiles x 2 K-halves)
// ---------------------------------------------------------------------------
__global__ void __launch_bounds__(256) k1_gemms(
    const float* __restrict__ x,
    const float* __restrict__ Wq, const float* __restrict__ Wk,
    const float* __restrict__ Wv)
{
    __shared__ float sm[8448];    // 33KB
    const int bx = blockIdx.x;
    if (bx < 256) {
        const int tile = bx >> 1, kc = bx & 1;
        gemm_half((const float4*)x, (const float4*)Wv, nullptr,
                  g_Vp[kc], (tile >> 3) << 5, (tile & 7) << 5, 256, 0, kc, sm);
    } else {
        const int q = bx - 256;
        const int tile = q >> 1, kc = q & 1;
        gemm_half((const float4*)x, (const float4*)Wq, (const float4*)Wk,
                  g_QKp[kc], (tile >> 1) << 5, (tile & 1) << 5, 64, 1, kc, sm);
    }
}

// ---------------------------------------------------------------------------
// Kernel 2: attention. 128 blocks = (bh, 32-row i-group), 256 threads.
// Sums the K-split partials + biases while staging. Inline trig.
// score(i,j) = prod_{w=1..3}( cos(th_w)cos(q_iw) - sin(th_w)sin(q_iw)cos(k_jw) )
// Scores bounded (|s|<=0.177) -> single-pass softmax.
// ---------------------------------------------------------------------------
__global__ void __launch_bounds__(256) attn_kernel(
    const float* __restrict__ ap,
    const float* __restrict__ bq, const float* __restrict__ bk,
    const float* __restrict__ bv)
{
    const int bx = blockIdx.x;
    const int ig = bx & 3;
    const int bh = bx >> 2;
    const int b = bh >> 3, h = bh & 7;

    __shared__ float4 Vs[1024];      // [j][p]
    __shared__ float4 CKs[128];
    __shared__ float  AB[32*6];
    __shared__ float  E[128*33];     // [j][il], pad 33
    __shared__ float  Psum[32*9];
    __shared__ float  Sinv[32];

    const int tid = threadIdx.x;
    const float4* V0 = (const float4*)g_Vp[0];
    const float4* V1 = (const float4*)g_Vp[1];
#pragma unroll
    for (int t = 0; t < 4; t++) {
        const int idx = tid + (t << 8);
        const int j = idx >> 3, p = idx & 7;
        const int gi = (b*Sx + j)*64 + h*8 + p;
        const float4 a  = V0[gi];
        const float4 c  = V1[gi];
        const float4 bb = *(const float4*)&bv[h*32 + p*4];
        Vs[idx] = make_float4(a.x + c.x + bb.x, a.y + c.y + bb.y,
                              a.z + c.z + bb.z, a.w + c.w + bb.w);
    }

    const float PI = 3.14159265358979323846f;
    if (tid < 128) {
        // k-side trig for row j
        const int j = tid;
        const int base = (b*Sx + j)*64 + h*8 + 4;
        float v[4];
#pragma unroll
        for (int q = 0; q < 4; q++)
            v[q] = g_QKp[0][base + q] + g_QKp[1][base + q] + bk[h*32 + q];
        const float mn = fminf(fminf(v[0], v[1]), fminf(v[2], v[3]));
        const float mx = fmaxf(fmaxf(v[0], v[1]), fmaxf(v[2], v[3]));
        const float sc = PI / (mx - mn + 1e-8f);
        CKs[j] = make_float4(cosf((v[1] - mn)*sc), cosf((v[2] - mn)*sc),
                             cosf((v[3] - mn)*sc), 0.f);
    } else if (tid < 160) {
        // q-side trig for row i
        const int il = tid - 128;
        const int i  = (ig << 5) + il;
        const int base = (b*Sx + i)*64 + h*8;
        float v[4];
#pragma unroll
        for (int q = 0; q < 4; q++)
            v[q] = g_QKp[0][base + q] + g_QKp[1][base + q] + bq[h*32 + q];
        const float mn = fminf(fminf(v[0], v[1]), fminf(v[2], v[3]));
        const float mx = fmaxf(fmaxf(v[0], v[1]), fmaxf(v[2], v[3]));
        const float sc = PI / (mx - mn + 1e-8f);
#pragma unroll
        for (int w = 0; w < 3; w++) {
            float sn, cs;
            sincosf((v[w + 1] - mn)*sc, &sn, &cs);
            const float th = ap[w + 1];
            AB[il*6 + w*2 + 0] = cosf(th) * cs;
            AB[il*6 + w*2 + 1] = sinf(th) * sn;
        }
    }
    __syncthreads();

    const int il = tid & 31;
    const int i  = (ig << 5) + il;

    // phase 1: exp scores; jg = tid>>5 handles 16 j's
    {
        const int jg = tid >> 5;
        const float A1 = AB[il*6+0], B1 = AB[il*6+1];
        const float A2 = AB[il*6+2], B2 = AB[il*6+3];
        const float A3 = AB[il*6+4], B3 = AB[il*6+5];
        const float SCALE = 0.17677669529663687f;   // 1/sqrt(32)
        float s = 0.f;
#pragma unroll
        for (int jj = 0; jj < 16; jj++) {
            const int j = (jg << 4) + jj;
            const float4 ck = CKs[j];
            const float sc = (A1 - B1*ck.x) * (A2 - B2*ck.y) * (A3 - B3*ck.z);
            const float e = __expf(sc * SCALE);
            E[j*33 + il] = e;
            s += e;
        }
        Psum[il*9 + jg] = s;
    }
    __syncthreads();
    if (tid < 32) {
        float s = 0.f;
#pragma unroll
        for (int jg = 0; jg < 8; jg++) s += Psum[tid*9 + jg];
        Sinv[tid] = 1.0f / s;
    }
    __syncthreads();

    // phase 2: p = tid>>5 owns one float4 dim-group (broadcast V loads)
    {
        const int p = tid >> 5;
        float4 o = make_float4(0.f, 0.f, 0.f, 0.f);
#pragma unroll 8
        for (int j = 0; j < 128; j++) {
            const float e = E[j*33 + il];
            const float4 v = Vs[(j << 3) + p];
            o.x = fmaf(e, v.x, o.x);
            o.y = fmaf(e, v.y, o.y);
            o.z = fmaf(e, v.z, o.z);
            o.w = fmaf(e, v.w, o.w);
        }
        const float inv = Sinv[il];
        o.x *= inv; o.y *= inv; o.z *= inv; o.w *= inv;
        ((float4*)g_AO)[(b*Sx + i)*64 + h*8 + p] = o;
    }
}

// ---------------------------------------------------------------------------
// Kernel 3: O-GEMM partials (256 blocks: 128 tiles x 2 K-halves)
// ---------------------------------------------------------------------------
__global__ void __launch_bounds__(256) k3_ogemm()
{
    __shared__ float sm[8448];
    const int bx = blockIdx.x;
    const int tile = bx >> 1, kc = bx & 1;
    extern __device__ float g_Wo_dummy[]; // placeholder (unused)
    (void)g_Wo_dummy;
    // Wo pointer passed via constant: use param version below instead
}

__global__ void __launch_bounds__(256) k3_ogemm_p(
    const float* __restrict__ Wo)
{
    __shared__ float sm[8448];
    const int bx = blockIdx.x;
    const int tile = bx >> 1, kc = bx & 1;
    gemm_half((const float4*)g_AO, (const float4*)Wo, nullptr,
              g_Op[kc], (tile >> 3) << 5, (tile & 7) << 5, 256, 0, kc, sm);
}

// ---------------------------------------------------------------------------
// Kernel 4: out = Op0 + Op1 + bo  (128 blocks x 256 thr, 1 float4 each)
// ---------------------------------------------------------------------------
__global__ void __launch_bounds__(256) k4_combine(
    const float* __restrict__ bo, float* __restrict__ out)
{
    const int i = blockIdx.x*256 + threadIdx.x;     // float4 index, 32768 total
    const float4 a  = ((const float4*)g_Op[0])[i];
    const float4 c  = ((const float4*)g_Op[1])[i];
    const float4 bb = ((const float4*)bo)[i & 63];
    ((float4*)out)[i] = make_float4(a.x + c.x + bb.x, a.y + c.y + bb.y,
                                    a.z + c.z + bb.z, a.w + c.w + bb.w);
}

// ---------------------------------------------------------------------------
extern "C" void kernel_launch(void* const* d_in, const int* in_sizes, int n_in,
                              void* d_out, int out_size)
{
    const float* x  = (const float*)d_in[0];
    const float* Wq = (const float*)d_in[1];
    const float* bq = (const float*)d_in[2];
    const float* Wk = (const float*)d_in[3];
    const float* bk = (const float*)d_in[4];
    const float* Wv = (const float*)d_in[5];
    const float* bv = (const float*)d_in[6];
    const float* Wo = (const float*)d_in[7];
    const float* bo = (const float*)d_in[8];
    const float* ap = (const float*)d_in[9];
    float* out = (float*)d_out;

    k1_gemms<<<320, 256>>>(x, Wq, Wk, Wv);
    attn_kernel<<<128, 256>>>(ap, bq, bk, bv);
    k3_ogemm_p<<<256, 256>>>(Wo);
    k4_combine<<<128, 256>>>(bo, out);
}